// round 15
// baseline (speedup 1.0000x reference)
#include <cuda_runtime.h>
#include <cuda_fp16.h>
#include <mma.h>
#include <cstdint>

using namespace nvcuda;

#define DM    512
#define NPOS  225
#define BMAX  64
#define MMAX  (BMAX*NPOS)
#define TE    12
#define DFF   2048

// ---------------- device scratch (static: no allocations allowed) ----------
__device__ __align__(16) float g_spe[NPOS*DM];
__device__ __align__(16) float g_ext[BMAX*DFF];
__device__ __align__(16) float g_exe[BMAX*DM];
__device__ __align__(16) float g_c1 [MMAX*DM];
__device__ __align__(16) float g_h  [MMAX*DM];
__device__ __align__(16) float g_tmp[MMAX*DM];
__device__ __align__(16) float g_o1 [MMAX*DM];
__device__ __align__(16) float g_o2 [MMAX*DM];
__device__ __align__(16) float g_bf [4*DM];
// fp16 activation mirrors / intermediates
__device__ __align__(16) __half g_col16[(size_t)MMAX*4608];
__device__ __align__(16) __half g_h16 [MMAX*DM];
__device__ __align__(16) __half g_o116[MMAX*DM];
__device__ __align__(16) __half g_o216[MMAX*DM];
__device__ __align__(16) __half g_xb16[MMAX*DM];
__device__ __align__(16) __half g_f116[(size_t)MMAX*DFF];
__device__ __align__(16) __half g_mm16[(size_t)MMAX*4096];
__device__ __align__(16) __half g_eb16[(size_t)MMAX*4096];
// fp16 weights
__device__ __align__(16) __half g_w2_16 [4608*512];
__device__ __align__(16) __half g_wv16  [4*512*512];
__device__ __align__(16) __half g_wo1_16[4*512*512];
__device__ __align__(16) __half g_wq16  [4*512*512];
__device__ __align__(16) __half g_wo2_16[4*512*512];
__device__ __align__(16) __half g_wkv16 [4*512*1024];
__device__ __align__(16) __half g_wkt16 [4*512*512];
__device__ __align__(16) __half g_f1w16 [4*512*2048];
__device__ __align__(16) __half g_f2w16 [4*2048*512];
__device__ __align__(16) __half g_wf16  [4*512*512];

__device__ __forceinline__ float gelu_f(float x){
    return 0.5f * x * (1.0f + erff(x * 0.70710678118654752f));
}

// ---------------- cp.async helpers ------------------------------------------
__device__ __forceinline__ void cp16(uint32_t dst, const void* src, int szbytes){
    asm volatile("cp.async.cg.shared.global [%0], [%1], 16, %2;\n"
                 :: "r"(dst), "l"(src), "r"(szbytes));
}
__device__ __forceinline__ void cp_commit(){
    asm volatile("cp.async.commit_group;\n");
}
template<int N> __device__ __forceinline__ void cp_wait(){
    asm volatile("cp.async.wait_group %0;\n" :: "n"(N));
}

// ---------------- conversion kernels ----------------------------------------
__global__ void cvt_kernel(__half* __restrict__ dst, const float* __restrict__ src, long n){
    for (long i = (long)blockIdx.x*blockDim.x + threadIdx.x; i < n;
         i += (long)gridDim.x*blockDim.x)
        dst[i] = __float2half(src[i]);
}
__global__ void wv16_kernel(const float* __restrict__ wx){
    int idx = blockIdx.x*blockDim.x + threadIdx.x;
    if (idx >= 4*512*512) return;
    int l = idx >> 18, rem = idx & 262143, k = rem >> 9, d = rem & 511;
    g_wv16[idx] = __float2half(wx[(long)l*786432 + k*1536 + 1024 + d]);
}
__global__ void wkt16_kernel(const float* __restrict__ wkv){
    int idx = blockIdx.x*blockDim.x + threadIdx.x;
    if (idx >= 4*512*512) return;
    int l = idx >> 18, rem = idx & 262143, hd = rem >> 9, c = rem & 511;
    g_wkt16[idx] = __float2half(wkv[(long)l*524288 + (long)c*1024 + hd]);
}

// ---------------- small kernels --------------------------------------------
__global__ void spe_kernel(){
    int p = blockIdx.x, i = threadIdx.x;
    float pr = (float)(p / 15 - 7);
    float pc = (float)(p % 15 - 7);
    float e  = (float)(2 * (i / 2)) / 512.0f;
    float rate = powf(10000.0f, -e);
    g_spe[p*DM + i] = (i & 1) ? cosf(pc * rate) : sinf(pr * rate);
}

__global__ void ex1_kernel(const float* __restrict__ ex,
                           const float* __restrict__ w,
                           const float* __restrict__ b){
    int bb = blockIdx.x;
    int j  = blockIdx.y * 256 + threadIdx.x;
    float acc = b[j];
#pragma unroll
    for (int k = 0; k < 64; k++) acc += ex[bb*64 + k] * w[k*DFF + j];
    g_ext[bb*DFF + j] = acc;
}

__global__ void ex2_kernel(const float* __restrict__ w,
                           const float* __restrict__ b){
    int bb = blockIdx.x;
    int j  = blockIdx.y * 256 + threadIdx.x;
    float acc = b[j];
    for (int k = 0; k < DFF; k++) acc += g_ext[bb*DFF + k] * w[k*DM + j];
    g_exe[bb*DM + j] = tanhf(acc);
}

__global__ void conv1_kernel(const float* __restrict__ xin,
                             const float* __restrict__ w,
                             const float* __restrict__ b, int M){
    int p = blockIdx.x; if (p >= M) return;
    int o = threadIdx.x;
    int bb = p / 225, yx = p % 225, y = yx / 15, x = yx % 15;
    float acc = b[o];
#pragma unroll
    for (int dy = 0; dy < 3; dy++){
        int yy = y + dy - 1; if (yy < 0 || yy >= 15) continue;
#pragma unroll
        for (int dx = 0; dx < 3; dx++){
            int xx = x + dx - 1; if (xx < 0 || xx >= 15) continue;
            const float* px = xin + ((bb*225 + yy*15 + xx) * 2);
            const float* pw = w + ((dy*3 + dx) * 2) * DM + o;
            acc += px[0] * pw[0] + px[1] * pw[DM];
        }
    }
    g_c1[(long)p*DM + o] = gelu_f(acc);
}

__global__ void im2col_kernel(int M){
    long total = (long)M * 4608;
    for (long idx = (long)blockIdx.x * blockDim.x + threadIdx.x; idx < total;
         idx += (long)gridDim.x * blockDim.x){
        int pos = (int)(idx / 4608); int r = (int)(idx % 4608);
        int patch = r >> 9; int c = r & 511;
        int dy = patch / 3, dx = patch % 3;
        int bb = pos / 225, yx = pos % 225, y = yx / 15, x = yx % 15;
        int yy = y + dy - 1, xx = x + dx - 1;
        float v = 0.0f;
        if (yy >= 0 && yy < 15 && xx >= 0 && xx < 15)
            v = g_c1[((long)(bb*225 + yy*15 + xx))*DM + c];
        g_col16[idx] = __float2half(v);
    }
}

__global__ void combine_kernel(int M){
    int p = blockIdx.x; if (p >= M) return;
    int c = threadIdx.x;
    int bb = p / 225, yx = p % 225;
    float v = g_tmp[(long)p*DM + c] * 22.62741699796952f
            + g_exe[bb*DM + c] + g_spe[yx*DM + c];
    g_h[(long)p*DM + c]   = v;
    g_h16[(long)p*DM + c] = __float2half(v);
}

__global__ void bf_kernel(const float* __restrict__ wxb,
                          const float* __restrict__ wo1w,
                          const float* __restrict__ wo1b){
    int l = blockIdx.x;
    int j = blockIdx.y * 256 + threadIdx.x;
    float acc = wo1b[l*DM + j];
    const float* bv = wxb + l*1536 + 1024;
    const float* w  = wo1w + (long)l*DM*DM;
    for (int k = 0; k < DM; k++) acc += bv[k] * w[k*DM + j];
    g_bf[l*DM + j] = acc;
}

// ---------------- fused cross-attention (T=1, S=12), fp32 enc (R9 proven) ---
__global__ __launch_bounds__(256) void cross_kernel(const float* __restrict__ enc,
                                                    const float* __restrict__ pm,
                                                    int M){
    __shared__ float es[TE*DM];
    int pos = blockIdx.x; if (pos >= M) return;
    const float4* src = (const float4*)(enc + (long)pos * TE * DM);
    float4* dst4 = (float4*)es;
    for (int i = threadIdx.x; i < TE*DM/4; i += 256) dst4[i] = src[i];
    __syncthreads();

    int h = threadIdx.x >> 5, lane = threadIdx.x & 31;
    float mr[16];
    const __half* mp = g_mm16 + (long)pos * 4096 + h * 512;
#pragma unroll
    for (int j = 0; j < 16; j++) mr[j] = __half2float(mp[lane + 32*j]);

    float lg[TE];
#pragma unroll
    for (int s = 0; s < TE; s++){
        float acc = 0.0f;
#pragma unroll
        for (int j = 0; j < 16; j++) acc += mr[j] * es[s*DM + lane + 32*j];
#pragma unroll
        for (int o = 16; o; o >>= 1) acc += __shfl_xor_sync(0xffffffffu, acc, o);
        lg[s] = acc * 0.125f + pm[s] * (-1e9f);
    }
    float mx = lg[0];
#pragma unroll
    for (int s = 1; s < TE; s++) mx = fmaxf(mx, lg[s]);
    float sum = 0.0f;
#pragma unroll
    for (int s = 0; s < TE; s++){ lg[s] = expf(lg[s] - mx); sum += lg[s]; }
    float inv = 1.0f / sum;

    __half* epo = g_eb16 + (long)pos * 4096 + h * 512;
#pragma unroll
    for (int j = 0; j < 16; j++){
        float e = 0.0f;
#pragma unroll
        for (int s = 0; s < TE; s++) e += lg[s] * es[s*DM + lane + 32*j];
        epo[lane + 32*j] = __float2half(e * inv);
    }
}

// ---------------- layernorm(residual), dual fp32+fp16 output ----------------
__device__ __forceinline__ float block_sum(float v, float* sbuf){
    __syncthreads();
#pragma unroll
    for (int o = 16; o; o >>= 1) v += __shfl_xor_sync(0xffffffffu, v, o);
    int wid = threadIdx.x >> 5, lane = threadIdx.x & 31;
    if (lane == 0) sbuf[wid] = v;
    __syncthreads();
    if (wid == 0){
        v = (lane < 8) ? sbuf[lane] : 0.0f;
#pragma unroll
        for (int o = 4; o; o >>= 1) v += __shfl_xor_sync(0xffffffffu, v, o);
        if (lane == 0) sbuf[0] = v;
    }
    __syncthreads();
    float r = sbuf[0];
    __syncthreads();
    return r;
}

__global__ __launch_bounds__(256) void ln_kernel(const float* __restrict__ a,
                                                 const float* __restrict__ b,
                                                 const float* __restrict__ g,
                                                 const float* __restrict__ be,
                                                 float* __restrict__ out,
                                                 __half* __restrict__ out16, int M){
    __shared__ float sbuf[8];
    int row = blockIdx.x; if (row >= M) return;
    long base = (long)row * DM;
    int t = threadIdx.x;
    float x0 = a[base + t]       + b[base + t];
    float x1 = a[base + t + 256] + b[base + t + 256];
    float s  = block_sum(x0 + x1, sbuf);
    float mean = s * (1.0f / 512.0f);
    float d0 = x0 - mean, d1 = x1 - mean;
    float q  = block_sum(d0*d0 + d1*d1, sbuf);
    float rstd = rsqrtf(q * (1.0f / 512.0f) + 1e-6f);
    float y0 = d0 * rstd * g[t]       + be[t];
    float y1 = d1 * rstd * g[t + 256] + be[t + 256];
    out[base + t]         = y0;
    out[base + t + 256]   = y1;
    out16[base + t]       = __float2half(y0);
    out16[base + t + 256] = __float2half(y1);
}

// ---------------- FP16 WMMA GEMM, 3-stage cp.async, wide warp tiles ---------
// C[z](MxN) = A[z](MxK fp16 row-major) @ B[z](KxN fp16 row-major) + bias(fp32)
// BM=128, BK=32, BN in {256,64}. 256 threads / 8 warps.
//   BN=256: warps 2x4, warp tile 64x64 (MF=4,NF=4)  [2.0 mma per frag load]
//   BN=64:  warps 4x2, warp tile 32x32 (MF=2,NF=2)
// HOUT=0: C fp32, direct fragment store.  HOUT=1: C fp16 via smem stage.
typedef wmma::fragment<wmma::matrix_a, 16, 16, 16, __half, wmma::row_major> FA;
typedef wmma::fragment<wmma::matrix_b, 16, 16, 16, __half, wmma::row_major> FB;
typedef wmma::fragment<wmma::accumulator, 16, 16, 16, float> FC;

template<int BN>
struct GCfg {
    static constexpr int STG  = 3;
    static constexpr int BKp  = 40;
    static constexpr int BNp  = BN + 8;
    static constexpr int NWn  = (BN == 256) ? 4 : 2;
    static constexpr int WPN  = BN / NWn;          // 64 or 32
    static constexpr int WM   = 128 / (8 / NWn);   // 64 or 32
    static constexpr int MF   = WM / 16;
    static constexpr int NF   = WPN / 16;
    static constexpr int ASTG = 128 * BKp;
    static constexpr int BSTG = 32 * BNp;
    static constexpr int BBI  = (32*(BN/8))/256;
    static constexpr int PIPE = STG*(ASTG + BSTG)*2;
    static constexpr int SMSZ = (PIPE > 128*72*4) ? PIPE : 128*72*4;
};

template<int BN, int EPI, int HOUT>
__global__ __launch_bounds__(256) void gemm_hh(
        const __half* __restrict__ A, long lda, long aZ,
        const __half* __restrict__ B, long ldb, long bZ,
        void* __restrict__ Cv, long ldc, long cZ,
        const float* __restrict__ bias, long biasZ,
        int M, int N, int K){
    using C = GCfg<BN>;
    extern __shared__ __align__(16) char smraw[];
    __half* As0 = (__half*)smraw;
    __half* Bs0 = As0 + C::STG*C::ASTG;

    const int tid = threadIdx.x, wid = tid >> 5;
    const int warpM = wid / C::NWn, warpN = wid % C::NWn;
    const int bm = blockIdx.y * 128, bn = blockIdx.x * BN, z = blockIdx.z;
    A += (long)z * aZ; B += (long)z * bZ;
    const float* bp = bias ? bias + (long)z * biasZ : nullptr;

    // ---- accumulators init from bias (staged at smem start) ----
    FC acc[C::MF][C::NF];
    {
        float* bstage = (float*)smraw;       // 16*BN floats
        for (int i = tid; i < 16*BN; i += 256)
            bstage[i] = bp ? bp[bn + (i % BN)] : 0.0f;
        __syncthreads();
#pragma unroll
        for (int i = 0; i < C::MF; i++)
#pragma unroll
            for (int j = 0; j < C::NF; j++)
                wmma::load_matrix_sync(acc[i][j], bstage + warpN*C::WPN + j*16,
                                       BN, wmma::mem_row_major);
        __syncthreads();
    }

    auto issue = [&](int kt){
        int k0 = kt * 32, st = kt % C::STG;
        __half* a = As0 + st*C::ASTG;
#pragma unroll
        for (int i = 0; i < 2; i++){
            int lin = tid + i*256, r = lin >> 2, q = (lin & 3) * 8;
            uint32_t dst = (uint32_t)__cvta_generic_to_shared(a + r*C::BKp + q);
            cp16(dst, A + (long)(bm + r)*lda + k0 + q, (bm + r < M) ? 16 : 0);
        }
        __half* b = Bs0 + st*C::BSTG;
#pragma unroll
        for (int i = 0; i < C::BBI; i++){
            int lin = tid + i*256, r = lin/(BN/8), q = (lin%(BN/8))*8;
            uint32_t dst = (uint32_t)__cvta_generic_to_shared(b + r*C::BNp + q);
            cp16(dst, B + (long)(k0 + r)*ldb + bn + q, 16);
        }
    };

    const int nk = K / 32;
    // prologue: fill STG-1 stages
#pragma unroll
    for (int s = 0; s < C::STG-1; s++){
        if (s < nk) issue(s);
        cp_commit();
    }

    for (int kt = 0; kt < nk; kt++){
        cp_wait<C::STG-2>();
        __syncthreads();
        if (kt + C::STG-1 < nk) issue(kt + C::STG-1);
        cp_commit();

        const __half* a = As0 + (kt % C::STG)*C::ASTG;
        const __half* b = Bs0 + (kt % C::STG)*C::BSTG;
#pragma unroll
        for (int ks = 0; ks < 32; ks += 16){
            FA fa[C::MF]; FB fb[C::NF];
#pragma unroll
            for (int i = 0; i < C::MF; i++)
                wmma::load_matrix_sync(fa[i], a + (warpM*C::WM + i*16)*C::BKp + ks, C::BKp);
#pragma unroll
            for (int j = 0; j < C::NF; j++)
                wmma::load_matrix_sync(fb[j], b + ks*C::BNp + warpN*C::WPN + j*16, C::BNp);
#pragma unroll
            for (int i = 0; i < C::MF; i++)
#pragma unroll
                for (int j = 0; j < C::NF; j++)
                    wmma::mma_sync(acc[i][j], fa[i], fb[j], acc[i][j]);
        }
    }
    cp_wait<0>();
    __syncthreads();

    if (HOUT == 0){
        float* Cp = (float*)Cv + (long)z * cZ;
#pragma unroll
        for (int i = 0; i < C::MF; i++){
            int row0 = bm + warpM*C::WM + i*16;
            if (row0 + 16 <= M){
#pragma unroll
                for (int j = 0; j < C::NF; j++){
                    if (EPI == 1){
#pragma unroll
                        for (int t = 0; t < acc[i][j].num_elements; t++)
                            acc[i][j].x[t] = gelu_f(acc[i][j].x[t]);
                    }
                    wmma::store_matrix_sync(Cp + (long)row0*ldc + bn + warpN*C::WPN + j*16,
                                            acc[i][j], ldc, wmma::mem_row_major);
                }
            }
        }
    } else {
        // fp16 output: stage 128x64 slabs through smem
        __half* Cp = (__half*)Cv + (long)z * cZ;
        float* stage = (float*)smraw;        // 128 x 72 floats
        constexpr int SLABS = (BN + 63) / 64;
        for (int sb = 0; sb < SLABS; sb++){
            __syncthreads();
            int colbase = warpN * C::WPN;    // within BN
            if (colbase >= sb*64 && colbase < sb*64 + 64){
                int lw = colbase - sb*64;
#pragma unroll
                for (int i = 0; i < C::MF; i++)
#pragma unroll
                    for (int j = 0; j < C::NF; j++)
                        wmma::store_matrix_sync(stage + (warpM*C::WM + i*16)*72 + lw + j*16,
                                                acc[i][j], 72, wmma::mem_row_major);
            }
            __syncthreads();
#pragma unroll
            for (int it = 0; it < 16; it++){
                int lin = tid + it*256, r = lin >> 5, c2 = lin & 31;
                int gr = bm + r, gc = bn + sb*64 + c2*2;
                if (gr < M){
                    float v0 = stage[r*72 + c2*2];
                    float v1 = stage[r*72 + c2*2 + 1];
                    if (EPI == 1){ v0 = gelu_f(v0); v1 = gelu_f(v1); }
                    *(__half2*)(Cp + (long)gr*ldc + gc) = __floats2half2_rn(v0, v1);
                }
            }
        }
    }
}

// ---------------- host side -------------------------------------------------
static void g256(const __half* A, long lda, long aZ,
                 const __half* B, long ldb, long bZ,
                 void* C, long ldc, long cZ,
                 const float* bias, long biasZ,
                 int M, int N, int K, int Z, int epi, int hout){
    dim3 grid(N / 256, (M + 127) / 128, Z);
    size_t shm = GCfg<256>::SMSZ;
    if (hout == 0){
        if (epi == 0) gemm_hh<256,0,0><<<grid,256,shm>>>(A,lda,aZ,B,ldb,bZ,C,ldc,cZ,bias,biasZ,M,N,K);
        else          gemm_hh<256,1,0><<<grid,256,shm>>>(A,lda,aZ,B,ldb,bZ,C,ldc,cZ,bias,biasZ,M,N,K);
    } else {
        if (epi == 0) gemm_hh<256,0,1><<<grid,256,shm>>>(A,lda,aZ,B,ldb,bZ,C,ldc,cZ,bias,biasZ,M,N,K);
        else          gemm_hh<256,1,1><<<grid,256,shm>>>(A,lda,aZ,B,ldb,bZ,C,ldc,cZ,bias,biasZ,M,N,K);
    }
}
static void g64h(const __half* A, long lda, long aZ,
                 const __half* B, long ldb, long bZ,
                 void* C, long ldc, long cZ,
                 const float* bias, long biasZ,
                 int M, int N, int K, int Z){
    dim3 grid(N / 64, (M + 127) / 128, Z);
    size_t shm = GCfg<64>::SMSZ;
    gemm_hh<64,0,1><<<grid,256,shm>>>(A,lda,aZ,B,ldb,bZ,C,ldc,cZ,bias,biasZ,M,N,K);
}

extern "C" void kernel_launch(void* const* d_in, const int* in_sizes, int n_in,
                              void* d_out, int out_size){
    const float* x        = (const float*)d_in[0];
    const float* ex       = (const float*)d_in[1];
    const float* enc      = (const float*)d_in[2];
    const float* pmask    = (const float*)d_in[4];
    const float* ex_w1    = (const float*)d_in[5];
    const float* ex_b1    = (const float*)d_in[6];
    const float* ex_w2    = (const float*)d_in[7];
    const float* ex_b2    = (const float*)d_in[8];
    const float* conv_w1  = (const float*)d_in[9];
    const float* conv_b1  = (const float*)d_in[10];
    const float* conv_w2  = (const float*)d_in[11];
    const float* conv_b2  = (const float*)d_in[12];
    const float* wx_w     = (const float*)d_in[13];
    const float* wx_b     = (const float*)d_in[14];
    const float* wo1_w    = (const float*)d_in[15];
    const float* wo1_b    = (const float*)d_in[16];
    const float* wq_w     = (const float*)d_in[17];
    const float* wq_b     = (const float*)d_in[18];
    const float* wkv_w    = (const float*)d_in[19];
    const float* wkv_b    = (const float*)d_in[20];
    const float* wo2_w    = (const float*)d_in[21];
    const float* wo2_b    = (const float*)d_in[22];
    const float* ffn_w1   = (const float*)d_in[23];
    const float* ffn_b1   = (const float*)d_in[24];
    const float* ffn_w2   = (const float*)d_in[25];
    const float* ffn_b2   = (const float*)d_in[26];
    const float* ln_g     = (const float*)d_in[27];
    const float* ln_b     = (const float*)d_in[28];

    int B = in_sizes[0] / 450;          // x = (B,15,15,1,2)
    if (B > BMAX) B = BMAX;
    int M = B * NPOS;

    // dynamic smem opt-in (host-side attr set; not a stream op, capture-safe)
    cudaFuncSetAttribute(gemm_hh<256,0,0>, cudaFuncAttributeMaxDynamicSharedMemorySize, GCfg<256>::SMSZ);
    cudaFuncSetAttribute(gemm_hh<256,1,0>, cudaFuncAttributeMaxDynamicSharedMemorySize, GCfg<256>::SMSZ);
    cudaFuncSetAttribute(gemm_hh<256,0,1>, cudaFuncAttributeMaxDynamicSharedMemorySize, GCfg<256>::SMSZ);
    cudaFuncSetAttribute(gemm_hh<256,1,1>, cudaFuncAttributeMaxDynamicSharedMemorySize, GCfg<256>::SMSZ);
    cudaFuncSetAttribute(gemm_hh<64,0,1>,  cudaFuncAttributeMaxDynamicSharedMemorySize, GCfg<64>::SMSZ);

    float *h, *tmp, *o1, *o2, *bf;
    __half *col16, *h16, *o116, *o216, *xb16, *f116, *mm16, *eb16;
    __half *w2_16, *wv16, *wo1_16, *wq16, *wo2_16, *wkv16, *wkt16, *f1w16, *f2w16, *wf16;
    cudaGetSymbolAddress((void**)&h,      g_h);
    cudaGetSymbolAddress((void**)&tmp,    g_tmp);
    cudaGetSymbolAddress((void**)&o1,     g_o1);
    cudaGetSymbolAddress((void**)&o2,     g_o2);
    cudaGetSymbolAddress((void**)&bf,     g_bf);
    cudaGetSymbolAddress((void**)&col16,  g_col16);
    cudaGetSymbolAddress((void**)&h16,    g_h16);
    cudaGetSymbolAddress((void**)&o116,   g_o116);
    cudaGetSymbolAddress((void**)&o216,   g_o216);
    cudaGetSymbolAddress((void**)&xb16,   g_xb16);
    cudaGetSymbolAddress((void**)&f116,   g_f116);
    cudaGetSymbolAddress((void**)&mm16,   g_mm16);
    cudaGetSymbolAddress((void**)&eb16,   g_eb16);
    cudaGetSymbolAddress((void**)&w2_16,  g_w2_16);
    cudaGetSymbolAddress((void**)&wv16,   g_wv16);
    cudaGetSymbolAddress((void**)&wo1_16, g_wo1_16);
    cudaGetSymbolAddress((void**)&wq16,   g_wq16);
    cudaGetSymbolAddress((void**)&wo2_16, g_wo2_16);
    cudaGetSymbolAddress((void**)&wkv16,  g_wkv16);
    cudaGetSymbolAddress((void**)&wkt16,  g_wkt16);
    cudaGetSymbolAddress((void**)&f1w16,  g_f1w16);
    cudaGetSymbolAddress((void**)&f2w16,  g_f2w16);
    cudaGetSymbolAddress((void**)&wf16,   g_wf16);

    // ---- one-time weight conversions to fp16 ----
    cvt_kernel<<<1024, 256>>>(w2_16,  conv_w2, 4608L*512);
    cvt_kernel<<<1024, 256>>>(wo1_16, wo1_w,   4L*262144);
    cvt_kernel<<<1024, 256>>>(wq16,   wq_w,    4L*262144);
    cvt_kernel<<<1024, 256>>>(wo2_16, wo2_w,   4L*262144);
    cvt_kernel<<<1024, 256>>>(wkv16,  wkv_w,   4L*524288);
    cvt_kernel<<<2048, 256>>>(f1w16,  ffn_w1,  4L*1048576);
    cvt_kernel<<<2048, 256>>>(f2w16,  ffn_w2,  4L*1048576);
    wv16_kernel <<<4096, 256>>>(wx_w);
    wkt16_kernel<<<4096, 256>>>(wkv_w);

    // ---- stem ----
    spe_kernel<<<NPOS, 512>>>();
    ex1_kernel<<<dim3(B, 8), 256>>>(ex, ex_w1, ex_b1);
    ex2_kernel<<<dim3(B, 2), 256>>>(ex_w2, ex_b2);
    conv1_kernel<<<M, 512>>>(x, conv_w1, conv_b1, M);
    im2col_kernel<<<4096, 256>>>(M);
    // conv2 as GEMM: (M x 4608)fp16 @ (4608 x 512)fp16 + b, gelu -> tmp fp32
    g256(col16, 4608, 0, w2_16, 512, 0, tmp, 512, 0, conv_b2, 0, M, 512, 4608, 1, 1, 0);
    combine_kernel<<<M, 512>>>(M);
    // fused self-attn weight: Wf_l = Wv_l @ Wo1_l -> fp16 (z = layer)
    g256(wv16, 512, 262144, wo1_16, 512, 262144,
         wf16, 512, 262144, nullptr, 0, 512, 512, 512, 4, 0, 1);
    bf_kernel<<<dim3(4, 2), 256>>>(wx_b, wo1_w, wo1_b);

    // ---- layers ----
    for (int l = 0; l < 4; l++){
        // self-attn (T=1): attn1 = h @ Wf + bf -> tmp fp32
        g256(h16, 512, 0, wf16 + (long)l*262144, 512, 0,
             tmp, 512, 0, bf + (long)l*512, 0, M, 512, 512, 1, 0, 0);
        ln_kernel<<<M, 256>>>(tmp, h, ln_g + (l*3+0)*512, ln_b + (l*3+0)*512, o1, o116, M);

        // q2 = o1 @ Wq + bq -> fp16
        g256(o116, 512, 0, wq16 + (long)l*262144, 512, 0,
             xb16, 512, 0, wq_b + (long)l*512, 0, M, 512, 512, 1, 0, 1);
        // m_h = q2_h @ Wk_h^T (8 heads via z) -> fp16
        g256(xb16, 512, 64, wkt16 + (long)l*262144, 512, 64*512,
             mm16, 4096, 512, nullptr, 0, M, 512, 64, 8, 0, 1);
        // logits + softmax + attention-weighted enc
        cross_kernel<<<M, 256>>>(enc, pmask, M);
        // o_h = ebar_h @ Wv_h + bv_h (8 heads via z) -> fp16
        g64h(eb16, 4096, 512, wkv16 + (long)l*524288 + 512, 1024, 64,
             xb16, 512, 64, wkv_b + (long)l*1024 + 512, 64, M, 64, 512, 8);
        // attn2 = xb @ Wo2 + bo2 -> tmp fp32
        g256(xb16, 512, 0, wo2_16 + (long)l*262144, 512, 0,
             tmp, 512, 0, wo2_b + (long)l*512, 0, M, 512, 512, 1, 0, 0);
        ln_kernel<<<M, 256>>>(tmp, o1, ln_g + (l*3+1)*512, ln_b + (l*3+1)*512, o2, o216, M);

        // FFN
        g256(o216, 512, 0, f1w16 + (long)l*1048576, 2048, 0,
             f116, 2048, 0, ffn_b1 + (long)l*2048, 0, M, 2048, 512, 1, 1, 1);
        g256(f116, 2048, 0, f2w16 + (long)l*1048576, 512, 0,
             tmp, 512, 0, ffn_b2 + (long)l*512, 0, M, 512, 2048, 1, 0, 0);
        float* outp = (l == 3) ? (float*)d_out : h;
        ln_kernel<<<M, 256>>>(tmp, o2, ln_g + (l*3+2)*512, ln_b + (l*3+2)*512, outp, h16, M);
    }
}

// round 16
// speedup vs baseline: 1.1564x; 1.1564x over previous
#include <cuda_runtime.h>
#include <cuda_fp16.h>
#include <mma.h>
#include <cstdint>

using namespace nvcuda;

#define DM    512
#define NPOS  225
#define BMAX  64
#define MMAX  (BMAX*NPOS)
#define TE    12
#define DFF   2048

// ---------------- device scratch (static: no allocations allowed) ----------
__device__ __align__(16) float g_spe[NPOS*DM];
__device__ __align__(16) float g_ext[BMAX*DFF];
__device__ __align__(16) float g_exe[BMAX*DM];
__device__ __align__(16) float g_c1 [MMAX*DM];
__device__ __align__(16) float g_h  [MMAX*DM];
__device__ __align__(16) float g_tmp[MMAX*DM];
__device__ __align__(16) float g_o1 [MMAX*DM];
__device__ __align__(16) float g_o2 [MMAX*DM];
__device__ __align__(16) float g_bf [4*DM];
// fp16 activation mirrors / intermediates
__device__ __align__(16) __half g_col16[(size_t)MMAX*4608];
__device__ __align__(16) __half g_h16 [MMAX*DM];
__device__ __align__(16) __half g_o116[MMAX*DM];
__device__ __align__(16) __half g_o216[MMAX*DM];
__device__ __align__(16) __half g_xb16[MMAX*DM];
__device__ __align__(16) __half g_f116[(size_t)MMAX*DFF];
__device__ __align__(16) __half g_mm16[(size_t)MMAX*4096];
__device__ __align__(16) __half g_eb16[(size_t)MMAX*4096];
// fp16 weights
__device__ __align__(16) __half g_w2_16 [4608*512];
__device__ __align__(16) __half g_wv16  [4*512*512];
__device__ __align__(16) __half g_wo1_16[4*512*512];
__device__ __align__(16) __half g_wq16  [4*512*512];
__device__ __align__(16) __half g_wo2_16[4*512*512];
__device__ __align__(16) __half g_wkv16 [4*512*1024];
__device__ __align__(16) __half g_wkt16 [4*512*512];
__device__ __align__(16) __half g_f1w16 [4*512*2048];
__device__ __align__(16) __half g_f2w16 [4*2048*512];
__device__ __align__(16) __half g_wf16  [4*512*512];

__device__ __forceinline__ float gelu_f(float x){
    return 0.5f * x * (1.0f + erff(x * 0.70710678118654752f));
}

// ---------------- cp.async helpers ------------------------------------------
__device__ __forceinline__ void cp16(uint32_t dst, const void* src, int szbytes){
    asm volatile("cp.async.cg.shared.global [%0], [%1], 16, %2;\n"
                 :: "r"(dst), "l"(src), "r"(szbytes));
}
__device__ __forceinline__ void cp_commit(){
    asm volatile("cp.async.commit_group;\n");
}
template<int N> __device__ __forceinline__ void cp_wait(){
    asm volatile("cp.async.wait_group %0;\n" :: "n"(N));
}

// ---------------- conversion kernels ----------------------------------------
__global__ void cvt_kernel(__half* __restrict__ dst, const float* __restrict__ src, long n){
    for (long i = (long)blockIdx.x*blockDim.x + threadIdx.x; i < n;
         i += (long)gridDim.x*blockDim.x)
        dst[i] = __float2half(src[i]);
}
__global__ void wv16_kernel(const float* __restrict__ wx){
    int idx = blockIdx.x*blockDim.x + threadIdx.x;
    if (idx >= 4*512*512) return;
    int l = idx >> 18, rem = idx & 262143, k = rem >> 9, d = rem & 511;
    g_wv16[idx] = __float2half(wx[(long)l*786432 + k*1536 + 1024 + d]);
}
__global__ void wkt16_kernel(const float* __restrict__ wkv){
    int idx = blockIdx.x*blockDim.x + threadIdx.x;
    if (idx >= 4*512*512) return;
    int l = idx >> 18, rem = idx & 262143, hd = rem >> 9, c = rem & 511;
    g_wkt16[idx] = __float2half(wkv[(long)l*524288 + (long)c*1024 + hd]);
}

// ---------------- small kernels --------------------------------------------
__global__ void spe_kernel(){
    int p = blockIdx.x, i = threadIdx.x;
    float pr = (float)(p / 15 - 7);
    float pc = (float)(p % 15 - 7);
    float e  = (float)(2 * (i / 2)) / 512.0f;
    float rate = powf(10000.0f, -e);
    g_spe[p*DM + i] = (i & 1) ? cosf(pc * rate) : sinf(pr * rate);
}

__global__ void ex1_kernel(const float* __restrict__ ex,
                           const float* __restrict__ w,
                           const float* __restrict__ b){
    int bb = blockIdx.x;
    int j  = blockIdx.y * 256 + threadIdx.x;
    float acc = b[j];
#pragma unroll
    for (int k = 0; k < 64; k++) acc += ex[bb*64 + k] * w[k*DFF + j];
    g_ext[bb*DFF + j] = acc;
}

__global__ void ex2_kernel(const float* __restrict__ w,
                           const float* __restrict__ b){
    int bb = blockIdx.x;
    int j  = blockIdx.y * 256 + threadIdx.x;
    float acc = b[j];
    for (int k = 0; k < DFF; k++) acc += g_ext[bb*DFF + k] * w[k*DM + j];
    g_exe[bb*DM + j] = tanhf(acc);
}

__global__ void conv1_kernel(const float* __restrict__ xin,
                             const float* __restrict__ w,
                             const float* __restrict__ b, int M){
    int p = blockIdx.x; if (p >= M) return;
    int o = threadIdx.x;
    int bb = p / 225, yx = p % 225, y = yx / 15, x = yx % 15;
    float acc = b[o];
#pragma unroll
    for (int dy = 0; dy < 3; dy++){
        int yy = y + dy - 1; if (yy < 0 || yy >= 15) continue;
#pragma unroll
        for (int dx = 0; dx < 3; dx++){
            int xx = x + dx - 1; if (xx < 0 || xx >= 15) continue;
            const float* px = xin + ((bb*225 + yy*15 + xx) * 2);
            const float* pw = w + ((dy*3 + dx) * 2) * DM + o;
            acc += px[0] * pw[0] + px[1] * pw[DM];
        }
    }
    g_c1[(long)p*DM + o] = gelu_f(acc);
}

__global__ void im2col_kernel(int M){
    long total = (long)M * 4608;
    for (long idx = (long)blockIdx.x * blockDim.x + threadIdx.x; idx < total;
         idx += (long)gridDim.x * blockDim.x){
        int pos = (int)(idx / 4608); int r = (int)(idx % 4608);
        int patch = r >> 9; int c = r & 511;
        int dy = patch / 3, dx = patch % 3;
        int bb = pos / 225, yx = pos % 225, y = yx / 15, x = yx % 15;
        int yy = y + dy - 1, xx = x + dx - 1;
        float v = 0.0f;
        if (yy >= 0 && yy < 15 && xx >= 0 && xx < 15)
            v = g_c1[((long)(bb*225 + yy*15 + xx))*DM + c];
        g_col16[idx] = __float2half(v);
    }
}

__global__ void combine_kernel(int M){
    int p = blockIdx.x; if (p >= M) return;
    int c = threadIdx.x;
    int bb = p / 225, yx = p % 225;
    float v = g_tmp[(long)p*DM + c] * 22.62741699796952f
            + g_exe[bb*DM + c] + g_spe[yx*DM + c];
    g_h[(long)p*DM + c]   = v;
    g_h16[(long)p*DM + c] = __float2half(v);
}

__global__ void bf_kernel(const float* __restrict__ wxb,
                          const float* __restrict__ wo1w,
                          const float* __restrict__ wo1b){
    int l = blockIdx.x;
    int j = blockIdx.y * 256 + threadIdx.x;
    float acc = wo1b[l*DM + j];
    const float* bv = wxb + l*1536 + 1024;
    const float* w  = wo1w + (long)l*DM*DM;
    for (int k = 0; k < DM; k++) acc += bv[k] * w[k*DM + j];
    g_bf[l*DM + j] = acc;
}

// ---------------- fused cross-attention (T=1, S=12), fp32 enc (R9 proven) ---
__global__ __launch_bounds__(256) void cross_kernel(const float* __restrict__ enc,
                                                    const float* __restrict__ pm,
                                                    int M){
    __shared__ float es[TE*DM];
    int pos = blockIdx.x; if (pos >= M) return;
    const float4* src = (const float4*)(enc + (long)pos * TE * DM);
    float4* dst4 = (float4*)es;
    for (int i = threadIdx.x; i < TE*DM/4; i += 256) dst4[i] = src[i];
    __syncthreads();

    int h = threadIdx.x >> 5, lane = threadIdx.x & 31;
    float mr[16];
    const __half* mp = g_mm16 + (long)pos * 4096 + h * 512;
#pragma unroll
    for (int j = 0; j < 16; j++) mr[j] = __half2float(mp[lane + 32*j]);

    float lg[TE];
#pragma unroll
    for (int s = 0; s < TE; s++){
        float acc = 0.0f;
#pragma unroll
        for (int j = 0; j < 16; j++) acc += mr[j] * es[s*DM + lane + 32*j];
#pragma unroll
        for (int o = 16; o; o >>= 1) acc += __shfl_xor_sync(0xffffffffu, acc, o);
        lg[s] = acc * 0.125f + pm[s] * (-1e9f);
    }
    float mx = lg[0];
#pragma unroll
    for (int s = 1; s < TE; s++) mx = fmaxf(mx, lg[s]);
    float sum = 0.0f;
#pragma unroll
    for (int s = 0; s < TE; s++){ lg[s] = expf(lg[s] - mx); sum += lg[s]; }
    float inv = 1.0f / sum;

    __half* epo = g_eb16 + (long)pos * 4096 + h * 512;
#pragma unroll
    for (int j = 0; j < 16; j++){
        float e = 0.0f;
#pragma unroll
        for (int s = 0; s < TE; s++) e += lg[s] * es[s*DM + lane + 32*j];
        epo[lane + 32*j] = __float2half(e * inv);
    }
}

// ---------------- layernorm(residual), dual fp32+fp16 output ----------------
__device__ __forceinline__ float block_sum(float v, float* sbuf){
    __syncthreads();
#pragma unroll
    for (int o = 16; o; o >>= 1) v += __shfl_xor_sync(0xffffffffu, v, o);
    int wid = threadIdx.x >> 5, lane = threadIdx.x & 31;
    if (lane == 0) sbuf[wid] = v;
    __syncthreads();
    if (wid == 0){
        v = (lane < 8) ? sbuf[lane] : 0.0f;
#pragma unroll
        for (int o = 4; o; o >>= 1) v += __shfl_xor_sync(0xffffffffu, v, o);
        if (lane == 0) sbuf[0] = v;
    }
    __syncthreads();
    float r = sbuf[0];
    __syncthreads();
    return r;
}

__global__ __launch_bounds__(256) void ln_kernel(const float* __restrict__ a,
                                                 const float* __restrict__ b,
                                                 const float* __restrict__ g,
                                                 const float* __restrict__ be,
                                                 float* __restrict__ out,
                                                 __half* __restrict__ out16, int M){
    __shared__ float sbuf[8];
    int row = blockIdx.x; if (row >= M) return;
    long base = (long)row * DM;
    int t = threadIdx.x;
    float x0 = a[base + t]       + b[base + t];
    float x1 = a[base + t + 256] + b[base + t + 256];
    float s  = block_sum(x0 + x1, sbuf);
    float mean = s * (1.0f / 512.0f);
    float d0 = x0 - mean, d1 = x1 - mean;
    float q  = block_sum(d0*d0 + d1*d1, sbuf);
    float rstd = rsqrtf(q * (1.0f / 512.0f) + 1e-6f);
    float y0 = d0 * rstd * g[t]       + be[t];
    float y1 = d1 * rstd * g[t + 256] + be[t + 256];
    out[base + t]         = y0;
    out[base + t + 256]   = y1;
    out16[base + t]       = __float2half(y0);
    out16[base + t + 256] = __float2half(y1);
}

// ---------------- FP16 WMMA GEMM, 3-stage cp.async (R13 config) -------------
// C[z](MxN) = A[z](MxK fp16 row-major) @ B[z](KxN fp16 row-major) + bias(fp32)
// BM=128, BK=32, BN in {128,64}. 256 threads / 8 warps.
// HOUT=0: C fp32, direct fragment store.
// HOUT=1: C fp16, direct fragment store via f32->f16 accumulator-fragment copy
//         (same logical element mapping for same-shape accumulator fragments).
typedef wmma::fragment<wmma::matrix_a, 16, 16, 16, __half, wmma::row_major> FA;
typedef wmma::fragment<wmma::matrix_b, 16, 16, 16, __half, wmma::row_major> FB;
typedef wmma::fragment<wmma::accumulator, 16, 16, 16, float> FC;
typedef wmma::fragment<wmma::accumulator, 16, 16, 16, __half> FCH;

template<int BN, int EPI, int HOUT>
__global__ __launch_bounds__(256) void gemm_hh(
        const __half* __restrict__ A, long lda, long aZ,
        const __half* __restrict__ B, long ldb, long bZ,
        void* __restrict__ Cv, long ldc, long cZ,
        const float* __restrict__ bias, long biasZ,
        int M, int N, int K){
    constexpr int STG = 3;
    constexpr int BKp = 40;                  // 32 + 8 halves pad (80B pitch, 16B-aligned)
    constexpr int BNp = BN + 8;
    constexpr int WM  = (BN == 128) ? 64 : 32;
    constexpr int NWn = BN / 32;
    constexpr int MF  = WM / 16;
    constexpr int NF  = 2;
    constexpr int ASTG = 128*BKp;            // halves per A stage
    constexpr int BSTG = 32*BNp;
    constexpr int BBI  = (32*(BN/8))/256;    // B 16B-chunks per thread
    constexpr int PIPE = STG*(ASTG + BSTG)*2;
    constexpr int BIAS = 16*BN*4;
    constexpr int SMSZ = (PIPE > BIAS) ? PIPE : BIAS;

    __shared__ __align__(16) char smraw[SMSZ];
    __half* As0 = (__half*)smraw;
    __half* Bs0 = As0 + STG*ASTG;

    const int tid = threadIdx.x, wid = tid >> 5;
    const int warpM = wid / NWn, warpN = wid % NWn;
    const int bm = blockIdx.y * 128, bn = blockIdx.x * BN, z = blockIdx.z;
    A += (long)z * aZ; B += (long)z * bZ;
    const float* bp = bias ? bias + (long)z * biasZ : nullptr;

    // ---- accumulators init from bias (staged at smem start) ----
    FC acc[MF][NF];
    {
        float* bstage = (float*)smraw;       // 16*BN floats
        for (int i = tid; i < 16*BN; i += 256)
            bstage[i] = bp ? bp[bn + (i % BN)] : 0.0f;
        __syncthreads();
#pragma unroll
        for (int i = 0; i < MF; i++)
#pragma unroll
            for (int j = 0; j < NF; j++)
                wmma::load_matrix_sync(acc[i][j], bstage + warpN*32 + j*16,
                                       BN, wmma::mem_row_major);
        __syncthreads();
    }

    auto issue = [&](int kt){
        int k0 = kt * 32, st = kt % STG;
        __half* a = As0 + st*ASTG;
#pragma unroll
        for (int i = 0; i < 2; i++){
            int lin = tid + i*256, r = lin >> 2, q = (lin & 3) * 8;
            uint32_t dst = (uint32_t)__cvta_generic_to_shared(a + r*BKp + q);
            cp16(dst, A + (long)(bm + r)*lda + k0 + q, (bm + r < M) ? 16 : 0);
        }
        __half* b = Bs0 + st*BSTG;
#pragma unroll
        for (int i = 0; i < BBI; i++){
            int lin = tid + i*256, r = lin/(BN/8), q = (lin%(BN/8))*8;
            uint32_t dst = (uint32_t)__cvta_generic_to_shared(b + r*BNp + q);
            cp16(dst, B + (long)(k0 + r)*ldb + bn + q, 16);
        }
    };

    const int nk = K / 32;
    // prologue: fill STG-1 stages
#pragma unroll
    for (int s = 0; s < STG-1; s++){
        if (s < nk) issue(s);
        cp_commit();
    }

    for (int kt = 0; kt < nk; kt++){
        cp_wait<STG-2>();
        __syncthreads();
        if (kt + STG-1 < nk) issue(kt + STG-1);
        cp_commit();

        const __half* a = As0 + (kt % STG)*ASTG;
        const __half* b = Bs0 + (kt % STG)*BSTG;
#pragma unroll
        for (int ks = 0; ks < 32; ks += 16){
            FA fa[MF]; FB fb[NF];
#pragma unroll
            for (int i = 0; i < MF; i++)
                wmma::load_matrix_sync(fa[i], a + (warpM*WM + i*16)*BKp + ks, BKp);
#pragma unroll
            for (int j = 0; j < NF; j++)
                wmma::load_matrix_sync(fb[j], b + ks*BNp + warpN*32 + j*16, BNp);
#pragma unroll
            for (int i = 0; i < MF; i++)
#pragma unroll
                for (int j = 0; j < NF; j++)
                    wmma::mma_sync(acc[i][j], fa[i], fb[j], acc[i][j]);
        }
    }
    cp_wait<0>();
    __syncthreads();

    if (HOUT == 0){
        float* C = (float*)Cv + (long)z * cZ;
#pragma unroll
        for (int i = 0; i < MF; i++){
            int row0 = bm + warpM*WM + i*16;
            if (row0 + 16 <= M){
#pragma unroll
                for (int j = 0; j < NF; j++){
                    if (EPI == 1){
#pragma unroll
                        for (int t = 0; t < acc[i][j].num_elements; t++)
                            acc[i][j].x[t] = gelu_f(acc[i][j].x[t]);
                    }
                    wmma::store_matrix_sync(C + (long)row0*ldc + bn + warpN*32 + j*16,
                                            acc[i][j], ldc, wmma::mem_row_major);
                }
            }
        }
    } else {
        // fp16 output: elementwise copy into half accumulator fragment, direct store
        __half* C = (__half*)Cv + (long)z * cZ;
#pragma unroll
        for (int i = 0; i < MF; i++){
            int row0 = bm + warpM*WM + i*16;
            if (row0 + 16 <= M){
#pragma unroll
                for (int j = 0; j < NF; j++){
                    FCH hacc;
#pragma unroll
                    for (int t = 0; t < acc[i][j].num_elements; t++){
                        float v = acc[i][j].x[t];
                        if (EPI == 1) v = gelu_f(v);
                        hacc.x[t] = __float2half(v);
                    }
                    wmma::store_matrix_sync(C + (long)row0*ldc + bn + warpN*32 + j*16,
                                            hacc, ldc, wmma::mem_row_major);
                }
            }
        }
    }
}

// ---------------- host side -------------------------------------------------
static void g128(const __half* A, long lda, long aZ,
                 const __half* B, long ldb, long bZ,
                 void* C, long ldc, long cZ,
                 const float* bias, long biasZ,
                 int M, int N, int K, int Z, int epi, int hout){
    dim3 grid(N / 128, (M + 127) / 128, Z);
    if (hout == 0){
        if (epi == 0) gemm_hh<128,0,0><<<grid,256>>>(A,lda,aZ,B,ldb,bZ,C,ldc,cZ,bias,biasZ,M,N,K);
        else          gemm_hh<128,1,0><<<grid,256>>>(A,lda,aZ,B,ldb,bZ,C,ldc,cZ,bias,biasZ,M,N,K);
    } else {
        if (epi == 0) gemm_hh<128,0,1><<<grid,256>>>(A,lda,aZ,B,ldb,bZ,C,ldc,cZ,bias,biasZ,M,N,K);
        else          gemm_hh<128,1,1><<<grid,256>>>(A,lda,aZ,B,ldb,bZ,C,ldc,cZ,bias,biasZ,M,N,K);
    }
}
static void g64h(const __half* A, long lda, long aZ,
                 const __half* B, long ldb, long bZ,
                 void* C, long ldc, long cZ,
                 const float* bias, long biasZ,
                 int M, int N, int K, int Z){
    dim3 grid(N / 64, (M + 127) / 128, Z);
    gemm_hh<64,0,1><<<grid,256>>>(A,lda,aZ,B,ldb,bZ,C,ldc,cZ,bias,biasZ,M,N,K);
}

extern "C" void kernel_launch(void* const* d_in, const int* in_sizes, int n_in,
                              void* d_out, int out_size){
    const float* x        = (const float*)d_in[0];
    const float* ex       = (const float*)d_in[1];
    const float* enc      = (const float*)d_in[2];
    const float* pmask    = (const float*)d_in[4];
    const float* ex_w1    = (const float*)d_in[5];
    const float* ex_b1    = (const float*)d_in[6];
    const float* ex_w2    = (const float*)d_in[7];
    const float* ex_b2    = (const float*)d_in[8];
    const float* conv_w1  = (const float*)d_in[9];
    const float* conv_b1  = (const float*)d_in[10];
    const float* conv_w2  = (const float*)d_in[11];
    const float* conv_b2  = (const float*)d_in[12];
    const float* wx_w     = (const float*)d_in[13];
    const float* wx_b     = (const float*)d_in[14];
    const float* wo1_w    = (const float*)d_in[15];
    const float* wo1_b    = (const float*)d_in[16];
    const float* wq_w     = (const float*)d_in[17];
    const float* wq_b     = (const float*)d_in[18];
    const float* wkv_w    = (const float*)d_in[19];
    const float* wkv_b    = (const float*)d_in[20];
    const float* wo2_w    = (const float*)d_in[21];
    const float* wo2_b    = (const float*)d_in[22];
    const float* ffn_w1   = (const float*)d_in[23];
    const float* ffn_b1   = (const float*)d_in[24];
    const float* ffn_w2   = (const float*)d_in[25];
    const float* ffn_b2   = (const float*)d_in[26];
    const float* ln_g     = (const float*)d_in[27];
    const float* ln_b     = (const float*)d_in[28];

    int B = in_sizes[0] / 450;          // x = (B,15,15,1,2)
    if (B > BMAX) B = BMAX;
    int M = B * NPOS;

    float *h, *tmp, *o1, *o2, *bf;
    __half *col16, *h16, *o116, *o216, *xb16, *f116, *mm16, *eb16;
    __half *w2_16, *wv16, *wo1_16, *wq16, *wo2_16, *wkv16, *wkt16, *f1w16, *f2w16, *wf16;
    cudaGetSymbolAddress((void**)&h,      g_h);
    cudaGetSymbolAddress((void**)&tmp,    g_tmp);
    cudaGetSymbolAddress((void**)&o1,     g_o1);
    cudaGetSymbolAddress((void**)&o2,     g_o2);
    cudaGetSymbolAddress((void**)&bf,     g_bf);
    cudaGetSymbolAddress((void**)&col16,  g_col16);
    cudaGetSymbolAddress((void**)&h16,    g_h16);
    cudaGetSymbolAddress((void**)&o116,   g_o116);
    cudaGetSymbolAddress((void**)&o216,   g_o216);
    cudaGetSymbolAddress((void**)&xb16,   g_xb16);
    cudaGetSymbolAddress((void**)&f116,   g_f116);
    cudaGetSymbolAddress((void**)&mm16,   g_mm16);
    cudaGetSymbolAddress((void**)&eb16,   g_eb16);
    cudaGetSymbolAddress((void**)&w2_16,  g_w2_16);
    cudaGetSymbolAddress((void**)&wv16,   g_wv16);
    cudaGetSymbolAddress((void**)&wo1_16, g_wo1_16);
    cudaGetSymbolAddress((void**)&wq16,   g_wq16);
    cudaGetSymbolAddress((void**)&wo2_16, g_wo2_16);
    cudaGetSymbolAddress((void**)&wkv16,  g_wkv16);
    cudaGetSymbolAddress((void**)&wkt16,  g_wkt16);
    cudaGetSymbolAddress((void**)&f1w16,  g_f1w16);
    cudaGetSymbolAddress((void**)&f2w16,  g_f2w16);
    cudaGetSymbolAddress((void**)&wf16,   g_wf16);

    // ---- one-time weight conversions to fp16 ----
    cvt_kernel<<<1024, 256>>>(w2_16,  conv_w2, 4608L*512);
    cvt_kernel<<<1024, 256>>>(wo1_16, wo1_w,   4L*262144);
    cvt_kernel<<<1024, 256>>>(wq16,   wq_w,    4L*262144);
    cvt_kernel<<<1024, 256>>>(wo2_16, wo2_w,   4L*262144);
    cvt_kernel<<<1024, 256>>>(wkv16,  wkv_w,   4L*524288);
    cvt_kernel<<<2048, 256>>>(f1w16,  ffn_w1,  4L*1048576);
    cvt_kernel<<<2048, 256>>>(f2w16,  ffn_w2,  4L*1048576);
    wv16_kernel <<<4096, 256>>>(wx_w);
    wkt16_kernel<<<4096, 256>>>(wkv_w);

    // ---- stem ----
    spe_kernel<<<NPOS, 512>>>();
    ex1_kernel<<<dim3(B, 8), 256>>>(ex, ex_w1, ex_b1);
    ex2_kernel<<<dim3(B, 2), 256>>>(ex_w2, ex_b2);
    conv1_kernel<<<M, 512>>>(x, conv_w1, conv_b1, M);
    im2col_kernel<<<4096, 256>>>(M);
    // conv2 as GEMM: (M x 4608)fp16 @ (4608 x 512)fp16 + b, gelu -> tmp fp32
    g128(col16, 4608, 0, w2_16, 512, 0, tmp, 512, 0, conv_b2, 0, M, 512, 4608, 1, 1, 0);
    combine_kernel<<<M, 512>>>(M);
    // fused self-attn weight: Wf_l = Wv_l @ Wo1_l -> fp16 (z = layer)
    g128(wv16, 512, 262144, wo1_16, 512, 262144,
         wf16, 512, 262144, nullptr, 0, 512, 512, 512, 4, 0, 1);
    bf_kernel<<<dim3(4, 2), 256>>>(wx_b, wo1_w, wo1_b);

    // ---- layers ----
    for (int l = 0; l < 4; l++){
        // self-attn (T=1): attn1 = h @ Wf + bf -> tmp fp32
        g128(h16, 512, 0, wf16 + (long)l*262144, 512, 0,
             tmp, 512, 0, bf + (long)l*512, 0, M, 512, 512, 1, 0, 0);
        ln_kernel<<<M, 256>>>(tmp, h, ln_g + (l*3+0)*512, ln_b + (l*3+0)*512, o1, o116, M);

        // q2 = o1 @ Wq + bq -> fp16
        g128(o116, 512, 0, wq16 + (long)l*262144, 512, 0,
             xb16, 512, 0, wq_b + (long)l*512, 0, M, 512, 512, 1, 0, 1);
        // m_h = q2_h @ Wk_h^T (8 heads via z) -> fp16
        g128(xb16, 512, 64, wkt16 + (long)l*262144, 512, 64*512,
             mm16, 4096, 512, nullptr, 0, M, 512, 64, 8, 0, 1);
        // logits + softmax + attention-weighted enc
        cross_kernel<<<M, 256>>>(enc, pmask, M);
        // o_h = ebar_h @ Wv_h + bv_h (8 heads via z) -> fp16
        g64h(eb16, 4096, 512, wkv16 + (long)l*524288 + 512, 1024, 64,
             xb16, 512, 64, wkv_b + (long)l*1024 + 512, 64, M, 64, 512, 8);
        // attn2 = xb @ Wo2 + bo2 -> tmp fp32
        g128(xb16, 512, 0, wo2_16 + (long)l*262144, 512, 0,
             tmp, 512, 0, wo2_b + (long)l*512, 0, M, 512, 512, 1, 0, 0);
        ln_kernel<<<M, 256>>>(tmp, o1, ln_g + (l*3+1)*512, ln_b + (l*3+1)*512, o2, o216, M);

        // FFN
        g128(o216, 512, 0, f1w16 + (long)l*1048576, 2048, 0,
             f116, 2048, 0, ffn_b1 + (long)l*2048, 0, M, 2048, 512, 1, 1, 1);
        g128(f116, 2048, 0, f2w16 + (long)l*1048576, 512, 0,
             tmp, 512, 0, ffn_b2 + (long)l*512, 0, M, 512, 2048, 1, 0, 0);
        float* outp = (l == 3) ? (float*)d_out : h;
        ln_kernel<<<M, 256>>>(tmp, o2, ln_g + (l*3+2)*512, ln_b + (l*3+2)*512, outp, h16, M);
    }
}

// round 17
// speedup vs baseline: 1.1853x; 1.0250x over previous
#include <cuda_runtime.h>
#include <cuda_fp16.h>
#include <mma.h>
#include <cstdint>

using namespace nvcuda;

#define DM    512
#define NPOS  225
#define BMAX  64
#define MMAX  (BMAX*NPOS)
#define TE    12
#define DFF   2048
#define PPOS  289   // padded 17x17

// ---------------- device scratch (static: no allocations allowed) ----------
__device__ __align__(16) float g_spe[NPOS*DM];
__device__ __align__(16) float g_ext[BMAX*DFF];
__device__ __align__(16) float g_exe[BMAX*DM];
__device__ __align__(16) float g_h  [MMAX*DM];
__device__ __align__(16) float g_tmp[MMAX*DM];
__device__ __align__(16) float g_o1 [MMAX*DM];
__device__ __align__(16) float g_o2 [MMAX*DM];
__device__ __align__(16) float g_bf [4*DM];
// fp16 activation mirrors / intermediates
__device__ __align__(16) __half g_c1p [(size_t)BMAX*PPOS*DM];  // padded conv1 out
__device__ __align__(16) __half g_h16 [MMAX*DM];
__device__ __align__(16) __half g_o116[MMAX*DM];
__device__ __align__(16) __half g_o216[MMAX*DM];
__device__ __align__(16) __half g_xb16[MMAX*DM];
__device__ __align__(16) __half g_f116[(size_t)MMAX*DFF];
__device__ __align__(16) __half g_mm16[(size_t)MMAX*4096];
__device__ __align__(16) __half g_eb16[(size_t)MMAX*4096];
// fp16 weights
__device__ __align__(16) __half g_w2_16 [4608*512];
__device__ __align__(16) __half g_wv16  [4*512*512];
__device__ __align__(16) __half g_wo1_16[4*512*512];
__device__ __align__(16) __half g_wq16  [4*512*512];
__device__ __align__(16) __half g_wo2_16[4*512*512];
__device__ __align__(16) __half g_wkv16 [4*512*1024];
__device__ __align__(16) __half g_wkt16 [4*512*512];
__device__ __align__(16) __half g_f1w16 [4*512*2048];
__device__ __align__(16) __half g_f2w16 [4*2048*512];
__device__ __align__(16) __half g_wf16  [4*512*512];

__device__ __forceinline__ float gelu_f(float x){
    return 0.5f * x * (1.0f + erff(x * 0.70710678118654752f));
}

// ---------------- cp.async helpers ------------------------------------------
__device__ __forceinline__ void cp16(uint32_t dst, const void* src, int szbytes){
    asm volatile("cp.async.cg.shared.global [%0], [%1], 16, %2;\n"
                 :: "r"(dst), "l"(src), "r"(szbytes));
}
__device__ __forceinline__ void cp_commit(){
    asm volatile("cp.async.commit_group;\n");
}
template<int N> __device__ __forceinline__ void cp_wait(){
    asm volatile("cp.async.wait_group %0;\n" :: "n"(N));
}

// ---------------- conversion kernels ----------------------------------------
__global__ void cvt_kernel(__half* __restrict__ dst, const float* __restrict__ src, long n){
    for (long i = (long)blockIdx.x*blockDim.x + threadIdx.x; i < n;
         i += (long)gridDim.x*blockDim.x)
        dst[i] = __float2half(src[i]);
}
__global__ void wv16_kernel(const float* __restrict__ wx){
    int idx = blockIdx.x*blockDim.x + threadIdx.x;
    if (idx >= 4*512*512) return;
    int l = idx >> 18, rem = idx & 262143, k = rem >> 9, d = rem & 511;
    g_wv16[idx] = __float2half(wx[(long)l*786432 + k*1536 + 1024 + d]);
}
__global__ void wkt16_kernel(const float* __restrict__ wkv){
    int idx = blockIdx.x*blockDim.x + threadIdx.x;
    if (idx >= 4*512*512) return;
    int l = idx >> 18, rem = idx & 262143, hd = rem >> 9, c = rem & 511;
    g_wkt16[idx] = __float2half(wkv[(long)l*524288 + (long)c*1024 + hd]);
}

// ---------------- small kernels --------------------------------------------
__global__ void spe_kernel(){
    int p = blockIdx.x, i = threadIdx.x;
    float pr = (float)(p / 15 - 7);
    float pc = (float)(p % 15 - 7);
    float e  = (float)(2 * (i / 2)) / 512.0f;
    float rate = powf(10000.0f, -e);
    g_spe[p*DM + i] = (i & 1) ? cosf(pc * rate) : sinf(pr * rate);
}

__global__ void ex1_kernel(const float* __restrict__ ex,
                           const float* __restrict__ w,
                           const float* __restrict__ b){
    int bb = blockIdx.x;
    int j  = blockIdx.y * 256 + threadIdx.x;
    float acc = b[j];
#pragma unroll
    for (int k = 0; k < 64; k++) acc += ex[bb*64 + k] * w[k*DFF + j];
    g_ext[bb*DFF + j] = acc;
}

__global__ void ex2_kernel(const float* __restrict__ w,
                           const float* __restrict__ b){
    int bb = blockIdx.x;
    int j  = blockIdx.y * 256 + threadIdx.x;
    float acc = b[j];
    for (int k = 0; k < DFF; k++) acc += g_ext[bb*DFF + k] * w[k*DM + j];
    g_exe[bb*DM + j] = tanhf(acc);
}

// conv1 -> zero-padded fp16 image (B,17,17,512); borders written as 0
__global__ void conv1p_kernel(const float* __restrict__ xin,
                              const float* __restrict__ w,
                              const float* __restrict__ b, int B){
    int p = blockIdx.x;                     // 0..B*289-1
    int o = threadIdx.x;
    int bb = p / PPOS, rem = p % PPOS, py = rem / 17, px = rem % 17;
    if (py == 0 || py == 16 || px == 0 || px == 16){
        g_c1p[(long)p*DM + o] = __float2half(0.0f);
        return;
    }
    int y = py - 1, x = px - 1;
    float acc = b[o];
#pragma unroll
    for (int dy = 0; dy < 3; dy++){
        int yy = y + dy - 1; if (yy < 0 || yy >= 15) continue;
#pragma unroll
        for (int dx = 0; dx < 3; dx++){
            int xx = x + dx - 1; if (xx < 0 || xx >= 15) continue;
            const float* pxp = xin + ((bb*225 + yy*15 + xx) * 2);
            const float* pw  = w + ((dy*3 + dx) * 2) * DM + o;
            acc += pxp[0] * pw[0] + pxp[1] * pw[DM];
        }
    }
    g_c1p[(long)p*DM + o] = __float2half(gelu_f(acc));
}

__global__ void combine_kernel(int M){
    int p = blockIdx.x; if (p >= M) return;
    int c = threadIdx.x;
    int bb = p / 225, yx = p % 225;
    float v = g_tmp[(long)p*DM + c] * 22.62741699796952f
            + g_exe[bb*DM + c] + g_spe[yx*DM + c];
    g_h[(long)p*DM + c]   = v;
    g_h16[(long)p*DM + c] = __float2half(v);
}

__global__ void bf_kernel(const float* __restrict__ wxb,
                          const float* __restrict__ wo1w,
                          const float* __restrict__ wo1b){
    int l = blockIdx.x;
    int j = blockIdx.y * 256 + threadIdx.x;
    float acc = wo1b[l*DM + j];
    const float* bv = wxb + l*1536 + 1024;
    const float* w  = wo1w + (long)l*DM*DM;
    for (int k = 0; k < DM; k++) acc += bv[k] * w[k*DM + j];
    g_bf[l*DM + j] = acc;
}

// ---------------- fused cross-attention (T=1, S=12), fp32 enc (R9 proven) ---
__global__ __launch_bounds__(256) void cross_kernel(const float* __restrict__ enc,
                                                    const float* __restrict__ pm,
                                                    int M){
    __shared__ float es[TE*DM];
    int pos = blockIdx.x; if (pos >= M) return;
    const float4* src = (const float4*)(enc + (long)pos * TE * DM);
    float4* dst4 = (float4*)es;
    for (int i = threadIdx.x; i < TE*DM/4; i += 256) dst4[i] = src[i];
    __syncthreads();

    int h = threadIdx.x >> 5, lane = threadIdx.x & 31;
    float mr[16];
    const __half* mp = g_mm16 + (long)pos * 4096 + h * 512;
#pragma unroll
    for (int j = 0; j < 16; j++) mr[j] = __half2float(mp[lane + 32*j]);

    float lg[TE];
#pragma unroll
    for (int s = 0; s < TE; s++){
        float acc = 0.0f;
#pragma unroll
        for (int j = 0; j < 16; j++) acc += mr[j] * es[s*DM + lane + 32*j];
#pragma unroll
        for (int o = 16; o; o >>= 1) acc += __shfl_xor_sync(0xffffffffu, acc, o);
        lg[s] = acc * 0.125f + pm[s] * (-1e9f);
    }
    float mx = lg[0];
#pragma unroll
    for (int s = 1; s < TE; s++) mx = fmaxf(mx, lg[s]);
    float sum = 0.0f;
#pragma unroll
    for (int s = 0; s < TE; s++){ lg[s] = expf(lg[s] - mx); sum += lg[s]; }
    float inv = 1.0f / sum;

    __half* epo = g_eb16 + (long)pos * 4096 + h * 512;
#pragma unroll
    for (int j = 0; j < 16; j++){
        float e = 0.0f;
#pragma unroll
        for (int s = 0; s < TE; s++) e += lg[s] * es[s*DM + lane + 32*j];
        epo[lane + 32*j] = __float2half(e * inv);
    }
}

// ---------------- layernorm(residual), dual fp32+fp16 output ----------------
__device__ __forceinline__ float block_sum(float v, float* sbuf){
    __syncthreads();
#pragma unroll
    for (int o = 16; o; o >>= 1) v += __shfl_xor_sync(0xffffffffu, v, o);
    int wid = threadIdx.x >> 5, lane = threadIdx.x & 31;
    if (lane == 0) sbuf[wid] = v;
    __syncthreads();
    if (wid == 0){
        v = (lane < 8) ? sbuf[lane] : 0.0f;
#pragma unroll
        for (int o = 4; o; o >>= 1) v += __shfl_xor_sync(0xffffffffu, v, o);
        if (lane == 0) sbuf[0] = v;
    }
    __syncthreads();
    float r = sbuf[0];
    __syncthreads();
    return r;
}

__global__ __launch_bounds__(256) void ln_kernel(const float* __restrict__ a,
                                                 const float* __restrict__ b,
                                                 const float* __restrict__ g,
                                                 const float* __restrict__ be,
                                                 float* __restrict__ out,
                                                 __half* __restrict__ out16, int M){
    __shared__ float sbuf[8];
    int row = blockIdx.x; if (row >= M) return;
    long base = (long)row * DM;
    int t = threadIdx.x;
    float x0 = a[base + t]       + b[base + t];
    float x1 = a[base + t + 256] + b[base + t + 256];
    float s  = block_sum(x0 + x1, sbuf);
    float mean = s * (1.0f / 512.0f);
    float d0 = x0 - mean, d1 = x1 - mean;
    float q  = block_sum(d0*d0 + d1*d1, sbuf);
    float rstd = rsqrtf(q * (1.0f / 512.0f) + 1e-6f);
    float y0 = d0 * rstd * g[t]       + be[t];
    float y1 = d1 * rstd * g[t + 256] + be[t + 256];
    out[base + t]         = y0;
    out[base + t + 256]   = y1;
    out16[base + t]       = __float2half(y0);
    out16[base + t + 256] = __float2half(y1);
}

// ---------------- FP16 WMMA GEMM, 3-stage cp.async (R15 config) -------------
// C[z](MxN) = A[z](MxK fp16 row-major) @ B[z](KxN fp16 row-major) + bias(fp32)
// BM=128, BK=32, BN in {128,64}. 256 threads / 8 warps.
// HOUT=0: C fp32 direct store. HOUT=1: C fp16 via f32->f16 fragment copy.
// CONV=1: A is the padded conv1 image (B,17,17,512); logical K=4608 with
//         row mapping (pos, k) -> c1p[bb*289 + (y+dy)*17 + (x+dx)][k&511].
typedef wmma::fragment<wmma::matrix_a, 16, 16, 16, __half, wmma::row_major> FA;
typedef wmma::fragment<wmma::matrix_b, 16, 16, 16, __half, wmma::row_major> FB;
typedef wmma::fragment<wmma::accumulator, 16, 16, 16, float> FC;
typedef wmma::fragment<wmma::accumulator, 16, 16, 16, __half> FCH;

template<int BN, int EPI, int HOUT, int CONV>
__global__ __launch_bounds__(256) void gemm_hh(
        const __half* __restrict__ A, long lda, long aZ,
        const __half* __restrict__ B, long ldb, long bZ,
        void* __restrict__ Cv, long ldc, long cZ,
        const float* __restrict__ bias, long biasZ,
        int M, int N, int K){
    constexpr int STG = 3;
    constexpr int BKp = 40;                  // 32 + 8 halves pad
    constexpr int BNp = BN + 8;
    constexpr int WM  = (BN == 128) ? 64 : 32;
    constexpr int NWn = BN / 32;
    constexpr int MF  = WM / 16;
    constexpr int NF  = 2;
    constexpr int ASTG = 128*BKp;
    constexpr int BSTG = 32*BNp;
    constexpr int BBI  = (32*(BN/8))/256;
    constexpr int PIPE = STG*(ASTG + BSTG)*2;
    constexpr int BIAS = 16*BN*4;
    constexpr int SMSZ = (PIPE > BIAS) ? PIPE : BIAS;

    __shared__ __align__(16) char smraw[SMSZ];
    __half* As0 = (__half*)smraw;
    __half* Bs0 = As0 + STG*ASTG;

    const int tid = threadIdx.x, wid = tid >> 5;
    const int warpM = wid / NWn, warpN = wid % NWn;
    const int bm = blockIdx.y * 128, bn = blockIdx.x * BN, z = blockIdx.z;
    A += (long)z * aZ; B += (long)z * bZ;
    const float* bp = bias ? bias + (long)z * biasZ : nullptr;

    // ---- accumulators init from bias (staged at smem start) ----
    FC acc[MF][NF];
    {
        float* bstage = (float*)smraw;
        for (int i = tid; i < 16*BN; i += 256)
            bstage[i] = bp ? bp[bn + (i % BN)] : 0.0f;
        __syncthreads();
#pragma unroll
        for (int i = 0; i < MF; i++)
#pragma unroll
            for (int j = 0; j < NF; j++)
                wmma::load_matrix_sync(acc[i][j], bstage + warpN*32 + j*16,
                                       BN, wmma::mem_row_major);
        __syncthreads();
    }

    auto issue = [&](int kt){
        int k0 = kt * 32, st = kt % STG;
        __half* a = As0 + st*ASTG;
#pragma unroll
        for (int i = 0; i < 2; i++){
            int lin = tid + i*256, r = lin >> 2, q = (lin & 3) * 8;
            int gr = bm + r;
            uint32_t dst = (uint32_t)__cvta_generic_to_shared(a + r*BKp + q);
            if (CONV){
                int grc = (gr < M) ? gr : 0;
                int patch = k0 >> 9, koff = k0 & 511;
                int dy = patch / 3, dx = patch % 3;
                int bb = grc / 225, yx = grc % 225, y = yx / 15, x = yx % 15;
                long prow = (long)bb*PPOS + (y + dy)*17 + (x + dx);
                cp16(dst, A + prow*512 + koff + q, (gr < M) ? 16 : 0);
            } else {
                cp16(dst, A + (long)gr*lda + k0 + q, (gr < M) ? 16 : 0);
            }
        }
        __half* b = Bs0 + st*BSTG;
#pragma unroll
        for (int i = 0; i < BBI; i++){
            int lin = tid + i*256, r = lin/(BN/8), q = (lin%(BN/8))*8;
            uint32_t dst = (uint32_t)__cvta_generic_to_shared(b + r*BNp + q);
            cp16(dst, B + (long)(k0 + r)*ldb + bn + q, 16);
        }
    };

    const int nk = K / 32;
#pragma unroll
    for (int s = 0; s < STG-1; s++){
        if (s < nk) issue(s);
        cp_commit();
    }

    for (int kt = 0; kt < nk; kt++){
        cp_wait<STG-2>();
        __syncthreads();
        if (kt + STG-1 < nk) issue(kt + STG-1);
        cp_commit();

        const __half* a = As0 + (kt % STG)*ASTG;
        const __half* b = Bs0 + (kt % STG)*BSTG;
#pragma unroll
        for (int ks = 0; ks < 32; ks += 16){
            FA fa[MF]; FB fb[NF];
#pragma unroll
            for (int i = 0; i < MF; i++)
                wmma::load_matrix_sync(fa[i], a + (warpM*WM + i*16)*BKp + ks, BKp);
#pragma unroll
            for (int j = 0; j < NF; j++)
                wmma::load_matrix_sync(fb[j], b + ks*BNp + warpN*32 + j*16, BNp);
#pragma unroll
            for (int i = 0; i < MF; i++)
#pragma unroll
                for (int j = 0; j < NF; j++)
                    wmma::mma_sync(acc[i][j], fa[i], fb[j], acc[i][j]);
        }
    }
    cp_wait<0>();
    __syncthreads();

    if (HOUT == 0){
        float* C = (float*)Cv + (long)z * cZ;
#pragma unroll
        for (int i = 0; i < MF; i++){
            int row0 = bm + warpM*WM + i*16;
            if (row0 + 16 <= M){
#pragma unroll
                for (int j = 0; j < NF; j++){
                    if (EPI == 1){
#pragma unroll
                        for (int t = 0; t < acc[i][j].num_elements; t++)
                            acc[i][j].x[t] = gelu_f(acc[i][j].x[t]);
                    }
                    wmma::store_matrix_sync(C + (long)row0*ldc + bn + warpN*32 + j*16,
                                            acc[i][j], ldc, wmma::mem_row_major);
                }
            }
        }
    } else {
        __half* C = (__half*)Cv + (long)z * cZ;
#pragma unroll
        for (int i = 0; i < MF; i++){
            int row0 = bm + warpM*WM + i*16;
            if (row0 + 16 <= M){
#pragma unroll
                for (int j = 0; j < NF; j++){
                    FCH hacc;
#pragma unroll
                    for (int t = 0; t < acc[i][j].num_elements; t++){
                        float v = acc[i][j].x[t];
                        if (EPI == 1) v = gelu_f(v);
                        hacc.x[t] = __float2half(v);
                    }
                    wmma::store_matrix_sync(C + (long)row0*ldc + bn + warpN*32 + j*16,
                                            hacc, ldc, wmma::mem_row_major);
                }
            }
        }
    }
}

// ---------------- host side -------------------------------------------------
static void g128(const __half* A, long lda, long aZ,
                 const __half* B, long ldb, long bZ,
                 void* C, long ldc, long cZ,
                 const float* bias, long biasZ,
                 int M, int N, int K, int Z, int epi, int hout){
    dim3 grid(N / 128, (M + 127) / 128, Z);
    if (hout == 0){
        if (epi == 0) gemm_hh<128,0,0,0><<<grid,256>>>(A,lda,aZ,B,ldb,bZ,C,ldc,cZ,bias,biasZ,M,N,K);
        else          gemm_hh<128,1,0,0><<<grid,256>>>(A,lda,aZ,B,ldb,bZ,C,ldc,cZ,bias,biasZ,M,N,K);
    } else {
        if (epi == 0) gemm_hh<128,0,1,0><<<grid,256>>>(A,lda,aZ,B,ldb,bZ,C,ldc,cZ,bias,biasZ,M,N,K);
        else          gemm_hh<128,1,1,0><<<grid,256>>>(A,lda,aZ,B,ldb,bZ,C,ldc,cZ,bias,biasZ,M,N,K);
    }
}
static void gconv(const __half* A,
                  const __half* B, long ldb,
                  void* C, long ldc,
                  const float* bias, int M){
    dim3 grid(512 / 128, (M + 127) / 128, 1);
    gemm_hh<128,1,0,1><<<grid,256>>>(A, 0, 0, B, ldb, 0, C, ldc, 0, bias, 0, M, 512, 4608);
}
static void g64h(const __half* A, long lda, long aZ,
                 const __half* B, long ldb, long bZ,
                 void* C, long ldc, long cZ,
                 const float* bias, long biasZ,
                 int M, int N, int K, int Z){
    dim3 grid(N / 64, (M + 127) / 128, Z);
    gemm_hh<64,0,1,0><<<grid,256>>>(A,lda,aZ,B,ldb,bZ,C,ldc,cZ,bias,biasZ,M,N,K);
}

extern "C" void kernel_launch(void* const* d_in, const int* in_sizes, int n_in,
                              void* d_out, int out_size){
    const float* x        = (const float*)d_in[0];
    const float* ex       = (const float*)d_in[1];
    const float* enc      = (const float*)d_in[2];
    const float* pmask    = (const float*)d_in[4];
    const float* ex_w1    = (const float*)d_in[5];
    const float* ex_b1    = (const float*)d_in[6];
    const float* ex_w2    = (const float*)d_in[7];
    const float* ex_b2    = (const float*)d_in[8];
    const float* conv_w1  = (const float*)d_in[9];
    const float* conv_b1  = (const float*)d_in[10];
    const float* conv_w2  = (const float*)d_in[11];
    const float* conv_b2  = (const float*)d_in[12];
    const float* wx_w     = (const float*)d_in[13];
    const float* wx_b     = (const float*)d_in[14];
    const float* wo1_w    = (const float*)d_in[15];
    const float* wo1_b    = (const float*)d_in[16];
    const float* wq_w     = (const float*)d_in[17];
    const float* wq_b     = (const float*)d_in[18];
    const float* wkv_w    = (const float*)d_in[19];
    const float* wkv_b    = (const float*)d_in[20];
    const float* wo2_w    = (const float*)d_in[21];
    const float* wo2_b    = (const float*)d_in[22];
    const float* ffn_w1   = (const float*)d_in[23];
    const float* ffn_b1   = (const float*)d_in[24];
    const float* ffn_w2   = (const float*)d_in[25];
    const float* ffn_b2   = (const float*)d_in[26];
    const float* ln_g     = (const float*)d_in[27];
    const float* ln_b     = (const float*)d_in[28];

    int B = in_sizes[0] / 450;          // x = (B,15,15,1,2)
    if (B > BMAX) B = BMAX;
    int M = B * NPOS;

    float *h, *tmp, *o1, *o2, *bf;
    __half *c1p, *h16, *o116, *o216, *xb16, *f116, *mm16, *eb16;
    __half *w2_16, *wv16, *wo1_16, *wq16, *wo2_16, *wkv16, *wkt16, *f1w16, *f2w16, *wf16;
    cudaGetSymbolAddress((void**)&h,      g_h);
    cudaGetSymbolAddress((void**)&tmp,    g_tmp);
    cudaGetSymbolAddress((void**)&o1,     g_o1);
    cudaGetSymbolAddress((void**)&o2,     g_o2);
    cudaGetSymbolAddress((void**)&bf,     g_bf);
    cudaGetSymbolAddress((void**)&c1p,    g_c1p);
    cudaGetSymbolAddress((void**)&h16,    g_h16);
    cudaGetSymbolAddress((void**)&o116,   g_o116);
    cudaGetSymbolAddress((void**)&o216,   g_o216);
    cudaGetSymbolAddress((void**)&xb16,   g_xb16);
    cudaGetSymbolAddress((void**)&f116,   g_f116);
    cudaGetSymbolAddress((void**)&mm16,   g_mm16);
    cudaGetSymbolAddress((void**)&eb16,   g_eb16);
    cudaGetSymbolAddress((void**)&w2_16,  g_w2_16);
    cudaGetSymbolAddress((void**)&wv16,   g_wv16);
    cudaGetSymbolAddress((void**)&wo1_16, g_wo1_16);
    cudaGetSymbolAddress((void**)&wq16,   g_wq16);
    cudaGetSymbolAddress((void**)&wo2_16, g_wo2_16);
    cudaGetSymbolAddress((void**)&wkv16,  g_wkv16);
    cudaGetSymbolAddress((void**)&wkt16,  g_wkt16);
    cudaGetSymbolAddress((void**)&f1w16,  g_f1w16);
    cudaGetSymbolAddress((void**)&f2w16,  g_f2w16);
    cudaGetSymbolAddress((void**)&wf16,   g_wf16);

    // ---- one-time weight conversions to fp16 ----
    cvt_kernel<<<1024, 256>>>(w2_16,  conv_w2, 4608L*512);
    cvt_kernel<<<1024, 256>>>(wo1_16, wo1_w,   4L*262144);
    cvt_kernel<<<1024, 256>>>(wq16,   wq_w,    4L*262144);
    cvt_kernel<<<1024, 256>>>(wo2_16, wo2_w,   4L*262144);
    cvt_kernel<<<1024, 256>>>(wkv16,  wkv_w,   4L*524288);
    cvt_kernel<<<2048, 256>>>(f1w16,  ffn_w1,  4L*1048576);
    cvt_kernel<<<2048, 256>>>(f2w16,  ffn_w2,  4L*1048576);
    wv16_kernel <<<4096, 256>>>(wx_w);
    wkt16_kernel<<<4096, 256>>>(wkv_w);

    // ---- stem ----
    spe_kernel<<<NPOS, 512>>>();
    ex1_kernel<<<dim3(B, 8), 256>>>(ex, ex_w1, ex_b1);
    ex2_kernel<<<dim3(B, 2), 256>>>(ex_w2, ex_b2);
    conv1p_kernel<<<B*PPOS, 512>>>(x, conv_w1, conv_b1, B);
    // conv2 as implicit GEMM on padded fp16 image (A in L2), gelu -> tmp fp32
    gconv(c1p, w2_16, 512, tmp, 512, conv_b2, M);
    combine_kernel<<<M, 512>>>(M);
    // fused self-attn weight: Wf_l = Wv_l @ Wo1_l -> fp16 (z = layer)
    g128(wv16, 512, 262144, wo1_16, 512, 262144,
         wf16, 512, 262144, nullptr, 0, 512, 512, 512, 4, 0, 1);
    bf_kernel<<<dim3(4, 2), 256>>>(wx_b, wo1_w, wo1_b);

    // ---- layers ----
    for (int l = 0; l < 4; l++){
        // self-attn (T=1): attn1 = h @ Wf + bf -> tmp fp32
        g128(h16, 512, 0, wf16 + (long)l*262144, 512, 0,
             tmp, 512, 0, bf + (long)l*512, 0, M, 512, 512, 1, 0, 0);
        ln_kernel<<<M, 256>>>(tmp, h, ln_g + (l*3+0)*512, ln_b + (l*3+0)*512, o1, o116, M);

        // q2 = o1 @ Wq + bq -> fp16
        g128(o116, 512, 0, wq16 + (long)l*262144, 512, 0,
             xb16, 512, 0, wq_b + (long)l*512, 0, M, 512, 512, 1, 0, 1);
        // m_h = q2_h @ Wk_h^T (8 heads via z) -> fp16
        g128(xb16, 512, 64, wkt16 + (long)l*262144, 512, 64*512,
             mm16, 4096, 512, nullptr, 0, M, 512, 64, 8, 0, 1);
        // logits + softmax + attention-weighted enc
        cross_kernel<<<M, 256>>>(enc, pmask, M);
        // o_h = ebar_h @ Wv_h + bv_h (8 heads via z) -> fp16
        g64h(eb16, 4096, 512, wkv16 + (long)l*524288 + 512, 1024, 64,
             xb16, 512, 64, wkv_b + (long)l*1024 + 512, 64, M, 64, 512, 8);
        // attn2 = xb @ Wo2 + bo2 -> tmp fp32
        g128(xb16, 512, 0, wo2_16 + (long)l*262144, 512, 0,
             tmp, 512, 0, wo2_b + (long)l*512, 0, M, 512, 512, 1, 0, 0);
        ln_kernel<<<M, 256>>>(tmp, o1, ln_g + (l*3+1)*512, ln_b + (l*3+1)*512, o2, o216, M);

        // FFN
        g128(o216, 512, 0, f1w16 + (long)l*1048576, 2048, 0,
             f116, 2048, 0, ffn_b1 + (long)l*2048, 0, M, 2048, 512, 1, 1, 1);
        g128(f116, 2048, 0, f2w16 + (long)l*1048576, 512, 0,
             tmp, 512, 0, ffn_b2 + (long)l*512, 0, M, 512, 2048, 1, 0, 0);
        float* outp = (l == 3) ? (float*)d_out : h;
        ln_kernel<<<M, 256>>>(tmp, o2, ln_g + (l*3+2)*512, ln_b + (l*3+2)*512, outp, h16, M);
    }
}